// round 1
// baseline (speedup 1.0000x reference)
#include <cuda_runtime.h>
#include <math.h>

#define Bb 8
#define Ll 39
#define Dd 256
#define DE 65536            // D*D
#define Mm 252
#define Ff 63504            // M*M
#define BL 312              // B*L
#define OUT_O 79872         // B*L*D
#define OUT_ATTN 12168      // B*L*L

// ---- scratch (device globals; no allocation allowed) ----
__device__ float g_scores[BL * Ll];              // 12168
__device__ float g_sumsq[BL];                    // 312
__device__ float g_out_acc[OUT_O];               // 79872
__device__ float g_x[(size_t)Bb * Ll * DE];      // 81.8 MB  post-attention maps
__device__ float g_e[(size_t)BL * Ff];           // 79.3 MB  tril(exp(conv)) rows

// ---------------------------------------------------------------------------
// init: zero accumulators
// ---------------------------------------------------------------------------
__global__ void init_kernel() {
    int i = blockIdx.x * 256 + threadIdx.x;
    if (i < BL * Ll) g_scores[i] = 0.f;
    if (i < BL)      g_sumsq[i] = 0.f;
    if (i < OUT_O)   g_out_acc[i] = 0.f;
}

// ---------------------------------------------------------------------------
// K1: Gram matrix  scores[b,i,j] = dot(H[b,i], H[b,j]) / 256
// grid (256 chunks, 8 b), block 256. smem-tiled 39 x 256 chunk, 3x3 reg tile.
// ---------------------------------------------------------------------------
__global__ __launch_bounds__(256) void gram_kernel(const float* __restrict__ H) {
    __shared__ float sh[Ll * 257];
    int b = blockIdx.y, ch = blockIdx.x;
    int t = threadIdx.x;
    const float* Hb = H + (size_t)b * Ll * DE + ch * 256;
    for (int idx = t; idx < Ll * 256; idx += 256) {
        int i = idx >> 8, c = idx & 255;
        sh[i * 257 + c] = Hb[(size_t)i * DE + c];
    }
    __syncthreads();
    int a = t >> 4, bb = t & 15;
    float acc[3][3] = {};
    for (int k = 0; k < 256; k++) {
        float ra[3], rb[3];
#pragma unroll
        for (int p = 0; p < 3; p++) { int i = a + 16 * p; ra[p] = sh[min(i, Ll - 1) * 257 + k]; }
#pragma unroll
        for (int q = 0; q < 3; q++) { int j = bb + 16 * q; rb[q] = sh[min(j, Ll - 1) * 257 + k]; }
#pragma unroll
        for (int p = 0; p < 3; p++)
#pragma unroll
            for (int q = 0; q < 3; q++) acc[p][q] += ra[p] * rb[q];
    }
#pragma unroll
    for (int p = 0; p < 3; p++)
#pragma unroll
        for (int q = 0; q < 3; q++) {
            int i = a + 16 * p, j = bb + 16 * q;
            if (i < Ll && j < Ll)
                atomicAdd(&g_scores[(b * Ll + i) * Ll + j], acc[p][q] * (1.f / 256.f));
        }
}

// ---------------------------------------------------------------------------
// K2: softmax over j (39), one warp per row, writes attention to d_out region
// ---------------------------------------------------------------------------
__global__ void softmax_kernel(float* __restrict__ attn) {
    int row = blockIdx.x;          // 0..311
    int lane = threadIdx.x;        // 32
    float v0 = g_scores[row * Ll + lane < row * Ll + Ll ? row * Ll + lane : row * Ll] ;
    v0 = (lane < Ll) ? g_scores[row * Ll + lane] : -1e30f;
    float v1 = (lane + 32 < Ll) ? g_scores[row * Ll + lane + 32] : -1e30f;
    float m = fmaxf(v0, v1);
#pragma unroll
    for (int off = 16; off; off >>= 1) m = fmaxf(m, __shfl_xor_sync(0xffffffffu, m, off));
    float e0 = (lane < Ll) ? expf(v0 - m) : 0.f;
    float e1 = (lane + 32 < Ll) ? expf(v1 - m) : 0.f;
    float s = e0 + e1;
#pragma unroll
    for (int off = 16; off; off >>= 1) s += __shfl_xor_sync(0xffffffffu, s, off);
    float inv = 1.f / s;
    if (lane < Ll) attn[row * Ll + lane] = e0 * inv;
    if (lane + 32 < Ll) attn[row * Ll + lane + 32] = e1 * inv;
}

// ---------------------------------------------------------------------------
// K3: x[b,i,de] = sum_j A[b,i,j] * H[b,j,de].  grid (256, 8), block 256.
// Each thread holds one de position, 39 accumulators over i. H read once.
// ---------------------------------------------------------------------------
__global__ __launch_bounds__(256) void attnapply_kernel(const float* __restrict__ H,
                                                        const float* __restrict__ attn) {
    int b = blockIdx.y;
    int pos = blockIdx.x * 256 + threadIdx.x;
    __shared__ float sA[Ll * Ll];
    for (int idx = threadIdx.x; idx < Ll * Ll; idx += 256)
        sA[idx] = attn[b * Ll * Ll + idx];
    __syncthreads();
    float acc[Ll];
#pragma unroll
    for (int i = 0; i < Ll; i++) acc[i] = 0.f;
    const float* Hb = H + (size_t)b * Ll * DE + pos;
#pragma unroll 1
    for (int j = 0; j < Ll; j++) {
        float h = Hb[(size_t)j * DE];
#pragma unroll
        for (int i = 0; i < Ll; i++) acc[i] += sA[i * Ll + j] * h;
    }
    float* xb = g_x + (size_t)b * Ll * DE + pos;
#pragma unroll
    for (int i = 0; i < Ll; i++) xb[(size_t)i * DE] = acc[i];
}

// ---------------------------------------------------------------------------
// K4: conv 5x5 (39 in ch -> 39 out ch, VALID) fused with +bias, exp, sumsq,
// tril mask. grid (4,4,312): 64x64 output tile per (b,o). block 256 = 16x16,
// each thread 4x4 outputs, 8x8 input register tile per channel.
// ---------------------------------------------------------------------------
__global__ __launch_bounds__(256, 2) void conv_kernel(const float* __restrict__ W,
                                                      const float* __restrict__ bias) {
    int bo = blockIdx.z;
    int b = bo / Ll, o = bo % Ll;
    int base_r = blockIdx.y * 64, base_c = blockIdx.x * 64;
    __shared__ float s_in[68 * 72];
    __shared__ float s_w[Ll * 25];
    __shared__ float ws[8];
    int t = threadIdx.x;
    for (int idx = t; idx < Ll * 25; idx += 256) s_w[idx] = W[o * (Ll * 25) + idx];
    const float* xb = g_x + (size_t)b * Ll * DE;
    int ty = t >> 4, tx = t & 15;
    int r0 = ty * 4, c0 = tx * 4;
    float acc[4][4] = {};
    for (int c = 0; c < Ll; c++) {
        __syncthreads();
        for (int idx = t; idx < 68 * 68; idx += 256) {
            int rr = idx / 68, cc = idx % 68;
            int gr = base_r + rr, gc = base_c + cc;
            float v = 0.f;
            if (gr < Dd && gc < Dd) v = xb[(size_t)c * DE + gr * Dd + gc];
            s_in[rr * 72 + cc] = v;
        }
        __syncthreads();
        float r[8][8];
#pragma unroll
        for (int i = 0; i < 8; i++) {
            float4 v0 = *(const float4*)&s_in[(r0 + i) * 72 + c0];
            float4 v1 = *(const float4*)&s_in[(r0 + i) * 72 + c0 + 4];
            r[i][0] = v0.x; r[i][1] = v0.y; r[i][2] = v0.z; r[i][3] = v0.w;
            r[i][4] = v1.x; r[i][5] = v1.y; r[i][6] = v1.z; r[i][7] = v1.w;
        }
        const float* wc = &s_w[c * 25];
#pragma unroll
        for (int kh = 0; kh < 5; kh++)
#pragma unroll
            for (int kw = 0; kw < 5; kw++) {
                float wv = wc[kh * 5 + kw];
#pragma unroll
                for (int i = 0; i < 4; i++)
#pragma unroll
                    for (int j = 0; j < 4; j++)
                        acc[i][j] += r[i + kh][j + kw] * wv;
            }
    }
    // epilogue: +bias, exp, sumsq (full matrix), tril store
    float bv = bias[o];
    float bsum = 0.f;
    size_t ebase = (size_t)bo * Ff;
#pragma unroll
    for (int i = 0; i < 4; i++)
#pragma unroll
        for (int j = 0; j < 4; j++) {
            int R = base_r + r0 + i, C = base_c + c0 + j;
            if (R < Mm && C < Mm) {
                float e = expf(acc[i][j] + bv);
                bsum += e * e;
                g_e[ebase + (size_t)R * Mm + C] = (R >= C) ? e : 0.f;
            }
        }
#pragma unroll
    for (int off = 16; off; off >>= 1) bsum += __shfl_down_sync(0xffffffffu, bsum, off);
    if ((t & 31) == 0) ws[t >> 5] = bsum;
    __syncthreads();
    if (t == 0) {
        float tot = 0.f;
#pragma unroll
        for (int w = 0; w < 8; w++) tot += ws[w];
        atomicAdd(&g_sumsq[bo], tot);
    }
}

// ---------------------------------------------------------------------------
// K5: Out[312,256] += E[312,63504] @ W2^T. 64x64 tiles, split-K=16 (chunk 3969),
// block 256, 4x4 micro-tile, atomicAdd accumulate.
// ---------------------------------------------------------------------------
#define KCH 3969
__global__ __launch_bounds__(256) void gemm_kernel(const float* __restrict__ W2) {
    __shared__ float sA[16 * 68];
    __shared__ float sB[16 * 68];
    int n0 = blockIdx.x * 64, m0 = blockIdx.y * 64;
    int k0 = blockIdx.z * KCH, kend = k0 + KCH;   // 16*3969 == 63504 exactly
    int t = threadIdx.x;
    int mt = 4 * (t >> 4), nt = 4 * (t & 15);
    float acc[4][4] = {};
    for (int kb = k0; kb < kend; kb += 16) {
        __syncthreads();
#pragma unroll
        for (int p = 0; p < 4; p++) {
            int idx = t + p * 256;
            int rl = idx >> 4, kl = idx & 15;
            int kk = kb + kl;
            int m = m0 + rl;
            float av = (m < BL && kk < kend) ? g_e[(size_t)m * Ff + kk] : 0.f;
            sA[kl * 68 + rl] = av;
            int n = n0 + rl;
            float bv = (kk < kend) ? W2[(size_t)n * Ff + kk] : 0.f;
            sB[kl * 68 + rl] = bv;
        }
        __syncthreads();
#pragma unroll
        for (int kk = 0; kk < 16; kk++) {
            float4 a = *(const float4*)&sA[kk * 68 + mt];
            float4 bv4 = *(const float4*)&sB[kk * 68 + nt];
            float am[4] = {a.x, a.y, a.z, a.w};
            float bn[4] = {bv4.x, bv4.y, bv4.z, bv4.w};
#pragma unroll
            for (int i = 0; i < 4; i++)
#pragma unroll
                for (int j = 0; j < 4; j++) acc[i][j] += am[i] * bn[j];
        }
    }
#pragma unroll
    for (int i = 0; i < 4; i++)
#pragma unroll
        for (int j = 0; j < 4; j++) {
            int m = m0 + mt + i, n = n0 + nt + j;
            if (m < BL) atomicAdd(&g_out_acc[m * Dd + n], acc[i][j]);
        }
}

// ---------------------------------------------------------------------------
// K6: finalize  out[m,n] = acc[m,n] * rsqrt(sumsq[m])
// ---------------------------------------------------------------------------
__global__ void finalize_kernel(float* __restrict__ out) {
    int idx = blockIdx.x * 256 + threadIdx.x;
    if (idx < OUT_O) {
        int m = idx >> 8;
        out[idx] = g_out_acc[idx] * rsqrtf(g_sumsq[m]);
    }
}

// ---------------------------------------------------------------------------
extern "C" void kernel_launch(void* const* d_in, const int* in_sizes, int n_in,
                              void* d_out, int out_size) {
    const float* hs     = (const float*)d_in[0];   // (8,39,256,256)
    const float* conv_w = (const float*)d_in[1];   // (512,39,5,5)
    const float* conv_b = (const float*)d_in[2];   // (512,)
    const float* out_w  = (const float*)d_in[3];   // (256,63504)
    float* out = (float*)d_out;                    // [out | attention]
    float* attn = out + OUT_O;

    init_kernel<<<(OUT_O + 255) / 256, 256>>>();
    gram_kernel<<<dim3(256, Bb), 256>>>(hs);
    softmax_kernel<<<BL, 32>>>(attn);
    attnapply_kernel<<<dim3(256, Bb), 256>>>(hs, attn);
    conv_kernel<<<dim3(4, 4, BL), 256>>>(conv_w, conv_b);
    gemm_kernel<<<dim3(4, 5, 16), 256>>>(out_w);
    finalize_kernel<<<(OUT_O + 255) / 256, 256>>>(out);
}